// round 2
// baseline (speedup 1.0000x reference)
#include <cuda_runtime.h>
#include <cuda_bf16.h>

// RFFT-1024 over 8192 rows (16x512x1024 fp32).
// Output: real[8192][513] followed by imag[8192][513] in d_out.
//
// Strategy: per-row complex radix-4 FFT in shared memory (5 stages).
// Base-4 digit-reversed load, one radix-4 butterfly per thread per stage.

#define NFFT 1024
#define NOUT 513
#define THREADS 256

__global__ void __launch_bounds__(THREADS)
rfft1024_kernel(const float* __restrict__ x,
                float* __restrict__ out_real,
                float* __restrict__ out_imag)
{
    __shared__ float sr[NFFT];
    __shared__ float si[NFFT];

    const int row = blockIdx.x;
    const float* __restrict__ xrow = x + (size_t)row * NFFT;
    const int t = threadIdx.x;

    // ---- load with base-4 digit reversal (5 digits of 2 bits) ----
#pragma unroll
    for (int j = 0; j < NFFT / THREADS; ++j) {
        int i = t + j * THREADS;
        int r = ((i & 3) << 8)
              | (((i >> 2) & 3) << 6)
              | (((i >> 4) & 3) << 4)
              | (((i >> 6) & 3) << 2)
              | ((i >> 8) & 3);
        sr[r] = xrow[i];
        si[r] = 0.0f;
    }
    __syncthreads();

    // ---- 5 radix-4 DIT stages (L = 1, 4, 16, 64, 256) ----
#pragma unroll
    for (int s = 0; s < 5; ++s) {
        const int L  = 1 << (2 * s);
        const int k  = t & (L - 1);          // position within sub-FFT
        const int g  = t >> (2 * s);         // group index
        const int i0 = g * (L << 2) + k;
        const int i1 = i0 + L;
        const int i2 = i0 + 2 * L;
        const int i3 = i0 + 3 * L;

        const float ang = -6.28318530717958647692f * (float)k / (float)(L << 2);
        float c1, s1, c2, s2, c3, s3;
        __sincosf(ang,        &s1, &c1);
        __sincosf(2.0f * ang, &s2, &c2);
        __sincosf(3.0f * ang, &s3, &c3);

        const float a0r = sr[i0], a0i = si[i0];
        const float a1r = sr[i1], a1i = si[i1];
        const float a2r = sr[i2], a2i = si[i2];
        const float a3r = sr[i3], a3i = si[i3];

        // twiddle multiplies: t_r = W^{rk} * a_r
        const float t1r = c1 * a1r - s1 * a1i;
        const float t1i = c1 * a1i + s1 * a1r;
        const float t2r = c2 * a2r - s2 * a2i;
        const float t2i = c2 * a2i + s2 * a2r;
        const float t3r = c3 * a3r - s3 * a3i;
        const float t3i = c3 * a3i + s3 * a3r;

        // radix-4 combine
        const float e0r = a0r + t2r, e0i = a0i + t2i;   // t0 + t2
        const float e1r = a0r - t2r, e1i = a0i - t2i;   // t0 - t2
        const float o0r = t1r + t3r, o0i = t1i + t3i;   // t1 + t3
        const float o1r = t1r - t3r, o1i = t1i - t3i;   // t1 - t3

        __syncthreads();  // ensure prior-stage reads done before overwrite? not needed:
                          // each thread owns {i0,i1,i2,i3} exclusively this stage.
                          // (kept minimal: see note below — actually placed between stages)

        sr[i0] = e0r + o0r;  si[i0] = e0i + o0i;          // X0 = e0 + o0
        sr[i1] = e1r + o1i;  si[i1] = e1i - o1r;          // X1 = e1 - i*o1
        sr[i2] = e0r - o0r;  si[i2] = e0i - o0i;          // X2 = e0 - o0
        sr[i3] = e1r - o1i;  si[i3] = e1i + o1r;          // X3 = e1 + i*o1

        __syncthreads();
    }

    // ---- store first 513 bins (real, then imag) ----
    float* __restrict__ orow = out_real + (size_t)row * NOUT;
    float* __restrict__ irow = out_imag + (size_t)row * NOUT;
#pragma unroll
    for (int j = 0; j < 3; ++j) {
        int k = t + j * THREADS;
        if (k < NOUT) {
            orow[k] = sr[k];
            irow[k] = si[k];
        }
    }
}

extern "C" void kernel_launch(void* const* d_in, const int* in_sizes, int n_in,
                              void* d_out, int out_size)
{
    const float* x = (const float*)d_in[0];
    float* out = (float*)d_out;
    const int n_rows = in_sizes[0] / NFFT;          // 8192
    float* out_real = out;
    float* out_imag = out + (size_t)n_rows * NOUT;  // real block first, imag second

    rfft1024_kernel<<<n_rows, THREADS>>>(x, out_real, out_imag);
}

// round 3
// speedup vs baseline: 3.2239x; 3.2239x over previous
#include <cuda_runtime.h>
#include <cuda_bf16.h>

// RFFT-1024 over 8192 rows (16x512x1024 fp32), output real[8192][513] ++ imag[8192][513].
//
// R2: real-pair packing (2 rows -> 1 complex FFT), padded conflict-free SMEM
// layout with per-stage butterfly permutations, 1 barrier per stage.

#define NFFT 1024
#define NOUT 513
#define THREADS 256

// padded physical index: stride-2^k access sets become conflict-free
__device__ __forceinline__ int P(int i) { return i + (i >> 5); }

__global__ void __launch_bounds__(THREADS)
rfft1024_packed_kernel(const float* __restrict__ x,
                       float* __restrict__ out_real,
                       float* __restrict__ out_imag)
{
    __shared__ float sr[NFFT + (NFFT >> 5)];   // 1056
    __shared__ float si[NFFT + (NFFT >> 5)];

    const int pair = blockIdx.x;
    const float* __restrict__ xa = x + (size_t)(2 * pair) * NFFT;
    const float* __restrict__ xb = xa + NFFT;
    const int t    = threadIdx.x;
    const int w    = t >> 5;
    const int lane = t & 31;

    // ---- packed load with base-4 digit reversal ----
#pragma unroll
    for (int j = 0; j < NFFT / THREADS; ++j) {
        int i = t + j * THREADS;
        int r = ((i & 3) << 8)
              | (((i >> 2) & 3) << 6)
              | (((i >> 4) & 3) << 4)
              | (((i >> 6) & 3) << 2)
              | ((i >> 8) & 3);
        int pr = P(r);
        sr[pr] = xa[i];          // real part  = row 2*pair
        si[pr] = xb[i];          // imag part  = row 2*pair+1
    }
    __syncthreads();

    // ---- 5 radix-4 DIT stages, conflict-free thread->butterfly mappings ----
#pragma unroll
    for (int s = 0; s < 5; ++s) {
        int b;
        if (s == 1) {
            // L=4:  g = 2*lane + (w>>2)  (0..63),  k = w&3
            b = (((lane << 1) + (w >> 2)) << 2) | (w & 3);
        } else if (s == 2) {
            // L=16: g = lane>>1 (0..15),  k = (lane&1) + 2*w (0..15)
            b = ((lane >> 1) << 4) | ((lane & 1) + (w << 1));
        } else {
            b = t;   // s=0,3,4: natural mapping is conflict-free under P()
        }

        const int L  = 1 << (2 * s);
        const int k  = b & (L - 1);
        const int g  = b >> (2 * s);
        const int i0 = g * (L << 2) + k;
        const int p0 = P(i0);
        const int p1 = P(i0 + L);
        const int p2 = P(i0 + 2 * L);
        const int p3 = P(i0 + 3 * L);

        const float ang = -6.28318530717958647692f * (float)k / (float)(L << 2);
        float c1, s1, c2, s2, c3, s3;
        __sincosf(ang,        &s1, &c1);
        __sincosf(2.0f * ang, &s2, &c2);
        __sincosf(3.0f * ang, &s3, &c3);

        const float a0r = sr[p0], a0i = si[p0];
        const float a1r = sr[p1], a1i = si[p1];
        const float a2r = sr[p2], a2i = si[p2];
        const float a3r = sr[p3], a3i = si[p3];

        const float t1r = c1 * a1r - s1 * a1i;
        const float t1i = c1 * a1i + s1 * a1r;
        const float t2r = c2 * a2r - s2 * a2i;
        const float t2i = c2 * a2i + s2 * a2r;
        const float t3r = c3 * a3r - s3 * a3i;
        const float t3i = c3 * a3i + s3 * a3r;

        const float e0r = a0r + t2r, e0i = a0i + t2i;
        const float e1r = a0r - t2r, e1i = a0i - t2i;
        const float o0r = t1r + t3r, o0i = t1i + t3i;
        const float o1r = t1r - t3r, o1i = t1i - t3i;

        // within a stage each thread owns {i0..i3} exclusively -> no mid-stage barrier
        sr[p0] = e0r + o0r;  si[p0] = e0i + o0i;
        sr[p1] = e1r + o1i;  si[p1] = e1i - o1r;
        sr[p2] = e0r - o0r;  si[p2] = e0i - o0i;
        sr[p3] = e1r - o1i;  si[p3] = e1i + o1r;

        __syncthreads();
    }

    // ---- Hermitian unpack: Z -> rfft(row 2p), rfft(row 2p+1) ----
    const size_t rA = (size_t)(2 * pair) * NOUT;
    const size_t rB = rA + NOUT;
#pragma unroll
    for (int j = 0; j < 3; ++j) {
        int k = t + j * THREADS;
        if (k < NOUT) {
            int m = (NFFT - k) & (NFFT - 1);
            float a = sr[P(k)], b2 = si[P(k)];
            float c = sr[P(m)], d  = si[P(m)];
            out_real[rA + k] = 0.5f * (a + c);     // Re Xa
            out_imag[rA + k] = 0.5f * (b2 - d);    // Im Xa
            out_real[rB + k] = 0.5f * (b2 + d);    // Re Xb
            out_imag[rB + k] = 0.5f * (c - a);     // Im Xb
        }
    }
}

extern "C" void kernel_launch(void* const* d_in, const int* in_sizes, int n_in,
                              void* d_out, int out_size)
{
    const float* x = (const float*)d_in[0];
    float* out = (float*)d_out;
    const int n_rows = in_sizes[0] / NFFT;          // 8192
    float* out_real = out;
    float* out_imag = out + (size_t)n_rows * NOUT;

    rfft1024_packed_kernel<<<n_rows / 2, THREADS>>>(x, out_real, out_imag);
}